// round 2
// baseline (speedup 1.0000x reference)
#include <cuda_runtime.h>
#include <math.h>

#define Bv 64
#define Tv 512
#define Dv 512
#define Uv 1024
#define Gv 4096   // 4*U
#define NBLK 128  // persistent blocks (<= 148 SMs, 1/SM via smem)

// Scratch (static device allocations are the sanctioned scratch mechanism)
__device__ float g_P[(size_t)Tv * Bv * Gv];   // 512 MiB: x-projection [t][b][4U]
__device__ float g_h[2][Bv * Uv];             // double-buffered hidden state
__device__ float g_c[Bv * Uv];                // cell state (block-private per unit)
__device__ int   g_count;                     // grid barrier arrive counter
__device__ int   g_release;                   // grid barrier release generation

// ---------------------------------------------------------------------------
// Reset state at the start of every replay (determinism across replays).
// ---------------------------------------------------------------------------
__global__ void init_kernel() {
    int i = blockIdx.x * blockDim.x + threadIdx.x;
    if (i < Bv * Uv) {
        g_h[0][i] = 0.0f;
        g_c[i]    = 0.0f;
    }
    if (i == 0) {
        g_count   = 0;
        g_release = 0;
    }
}

// ---------------------------------------------------------------------------
// x-projection GEMM: P[t*64+b][n] = sum_d x[b][t][d] * Wx[d][n] + bias[n]
// M = T*B = 32768 (m = t*64+b), N = 4096, K = 512.
// Block tile 64x64, BK=16, 256 threads, 4x4 register micro-tile.
// ---------------------------------------------------------------------------
__global__ __launch_bounds__(256) void xproj_kernel(
    const float* __restrict__ x,
    const float* __restrict__ Wx,
    const float* __restrict__ bias,
    float* __restrict__ P)
{
    __shared__ float As[16][65];  // [k][m], padded
    __shared__ float Bs[16][64];  // [k][n]

    int tid = threadIdx.x;
    int n0  = blockIdx.x * 64;
    int m0  = blockIdx.y * 64;
    int t   = m0 >> 6;            // all 64 rows of this block share t; b = row

    int a_row = tid >> 2;
    int a_c   = (tid & 3) * 4;
    const float* xrow = x + (size_t)a_row * Tv * Dv + (size_t)t * Dv;

    int b_row = tid >> 4;
    int b_c   = (tid & 15) * 4;

    int tx = tid & 15;
    int ty = tid >> 4;

    float acc[4][4];
#pragma unroll
    for (int i = 0; i < 4; i++)
#pragma unroll
        for (int j = 0; j < 4; j++) acc[i][j] = 0.0f;

    for (int kc = 0; kc < Dv; kc += 16) {
        float4 av = *(const float4*)(xrow + kc + a_c);
        As[a_c + 0][a_row] = av.x;
        As[a_c + 1][a_row] = av.y;
        As[a_c + 2][a_row] = av.z;
        As[a_c + 3][a_row] = av.w;
        float4 bv = *(const float4*)(Wx + (size_t)(kc + b_row) * Gv + n0 + b_c);
        *(float4*)&Bs[b_row][b_c] = bv;
        __syncthreads();

#pragma unroll
        for (int k = 0; k < 16; k++) {
            float a0 = As[k][ty * 4 + 0];
            float a1 = As[k][ty * 4 + 1];
            float a2 = As[k][ty * 4 + 2];
            float a3 = As[k][ty * 4 + 3];
            float4 b4 = *(const float4*)&Bs[k][tx * 4];
            acc[0][0] += a0 * b4.x; acc[0][1] += a0 * b4.y; acc[0][2] += a0 * b4.z; acc[0][3] += a0 * b4.w;
            acc[1][0] += a1 * b4.x; acc[1][1] += a1 * b4.y; acc[1][2] += a1 * b4.z; acc[1][3] += a1 * b4.w;
            acc[2][0] += a2 * b4.x; acc[2][1] += a2 * b4.y; acc[2][2] += a2 * b4.z; acc[2][3] += a2 * b4.w;
            acc[3][0] += a3 * b4.x; acc[3][1] += a3 * b4.y; acc[3][2] += a3 * b4.z; acc[3][3] += a3 * b4.w;
        }
        __syncthreads();
    }

    float4 bb = *(const float4*)(bias + n0 + tx * 4);
#pragma unroll
    for (int i = 0; i < 4; i++) {
        float4 o;
        o.x = acc[i][0] + bb.x;
        o.y = acc[i][1] + bb.y;
        o.z = acc[i][2] + bb.z;
        o.w = acc[i][3] + bb.w;
        *(float4*)(P + (size_t)(m0 + ty * 4 + i) * Gv + n0 + tx * 4) = o;
    }
}

// ---------------------------------------------------------------------------
// Persistent LSTM recurrence. 128 blocks x 256 threads, 1 block/SM.
// Block bu owns hidden units [bu*8, bu*8+8) -> 32 gate columns.
// Wh slice [1024][32] is loaded into SMEM ONCE and reused for all 512 steps.
// Per step: gates[64][32] = h @ Wh_slice (2x4 micro-tile, h-chunk prefetch),
// fused LSTM pointwise, then grid-wide sense barrier.
// Dynamic SMEM: ws 1024*32 | hs 64*68 | gs 64*33  = 156,928 B.
// ---------------------------------------------------------------------------
__global__ __launch_bounds__(256) void lstm_persist_kernel(
    const float* __restrict__ Wh,
    float* __restrict__ out)
{
    extern __shared__ float sm[];
    float* ws = sm;                       // [1024][32]
    float* hs = sm + 32768;               // [64][68] (padded)
    float* gs = sm + 32768 + 64 * 68;     // [64][33] (padded)

    int tid    = threadIdx.x;
    int u_base = blockIdx.x * 8;

    // One-time: load this block's Wh slice into SMEM.
    // local col lc = gate*8 + j  <->  global col n = gate*1024 + u_base + j
    for (int i = tid; i < 8192; i += 256) {
        int k = i >> 3;
        int q = i & 7;  // gate = q>>1, half = q&1
        float4 v = *(const float4*)(Wh + (size_t)k * Gv + (q >> 1) * Uv + u_base + (q & 1) * 4);
        *(float4*)&ws[k * 32 + (q >> 1) * 8 + (q & 1) * 4] = v;
    }
    __syncthreads();

    int tx = tid & 7;     // col group (0..7)
    int ty = tid >> 3;    // row group (0..31)
    int c0 = tx * 4;
    int r0 = ty * 2;

    for (int t = 0; t < Tv; t++) {
        const float* hin  = g_h[t & 1];
        float*       hout = g_h[(t + 1) & 1];

        float acc[2][4];
#pragma unroll
        for (int i = 0; i < 2; i++)
#pragma unroll
            for (int j = 0; j < 4; j++) acc[i][j] = 0.0f;

        // prefetch h chunk 0 into registers
        float4 pre[4];
#pragma unroll
        for (int i = 0; i < 4; i++) {
            int idx = tid + i * 256;
            pre[i] = *(const float4*)(hin + (idx >> 4) * Uv + ((idx & 15) << 2));
        }

        for (int kc = 0; kc < Uv; kc += 64) {
            // commit prefetched chunk to SMEM
#pragma unroll
            for (int i = 0; i < 4; i++) {
                int idx = tid + i * 256;
                *(float4*)&hs[(idx >> 4) * 68 + ((idx & 15) << 2)] = pre[i];
            }
            __syncthreads();

            // prefetch next chunk (LDG latency overlaps FFMA loop)
            if (kc + 64 < Uv) {
#pragma unroll
                for (int i = 0; i < 4; i++) {
                    int idx = tid + i * 256;
                    pre[i] = *(const float4*)(hin + (idx >> 4) * Uv + kc + 64 + ((idx & 15) << 2));
                }
            }

#pragma unroll 8
            for (int kk = 0; kk < 64; kk++) {
                float4 wv = *(const float4*)&ws[(kc + kk) * 32 + c0];
                float h0 = hs[r0 * 68 + kk];
                float h1 = hs[(r0 + 1) * 68 + kk];
                acc[0][0] += h0 * wv.x; acc[0][1] += h0 * wv.y;
                acc[0][2] += h0 * wv.z; acc[0][3] += h0 * wv.w;
                acc[1][0] += h1 * wv.x; acc[1][1] += h1 * wv.y;
                acc[1][2] += h1 * wv.z; acc[1][3] += h1 * wv.w;
            }
            __syncthreads();
        }

        // park raw gates in SMEM so each (b, unit) pair can gather its 4 gates
#pragma unroll
        for (int j = 0; j < 4; j++) {
            gs[r0 * 33 + c0 + j]       = acc[0][j];
            gs[(r0 + 1) * 33 + c0 + j] = acc[1][j];
        }
        __syncthreads();

        // pointwise LSTM cell: 64 batches x 8 units = 512 pairs, 2 per thread
        const float* Pt = g_P + (size_t)t * Bv * Gv;
#pragma unroll
        for (int p = tid; p < 512; p += 256) {
            int b = p >> 3;
            int j = p & 7;
            int u = u_base + j;
            const float* Pb = Pt + (size_t)b * Gv;

            float xi = gs[b * 33 + j]      + Pb[u];
            float xf = gs[b * 33 + 8 + j]  + Pb[Uv + u];
            float xg = gs[b * 33 + 16 + j] + Pb[2 * Uv + u];
            float xo = gs[b * 33 + 24 + j] + Pb[3 * Uv + u];

            float ig = 1.0f / (1.0f + expf(-xi));
            float fg = 1.0f / (1.0f + expf(-xf));
            float gg = tanhf(xg);
            float og = 1.0f / (1.0f + expf(-xo));

            int idx = b * Uv + u;
            float c = fg * g_c[idx] + ig * gg;
            g_c[idx] = c;
            float h = og * tanhf(c);
            hout[idx] = h;
            out[((size_t)b * Tv + t) * Uv + u] = h;
        }

        // grid-wide barrier: all blocks must finish step t before t+1
        __syncthreads();
        if (tid == 0) {
            __threadfence();
            int v = atomicAdd(&g_count, 1);
            if (v == NBLK - 1) {
                g_count = 0;
                __threadfence();
                atomicExch(&g_release, t + 1);
            } else {
                volatile int* rel = &g_release;
                while (*rel < t + 1) { }
                __threadfence();
            }
        }
        __syncthreads();
    }
}

// ---------------------------------------------------------------------------
// Launch: init -> xproj -> ONE persistent recurrence kernel.
// ---------------------------------------------------------------------------
extern "C" void kernel_launch(void* const* d_in, const int* in_sizes, int n_in,
                              void* d_out, int out_size)
{
    const float* x    = (const float*)d_in[0];   // [64, 512, 512]
    const float* Wx   = (const float*)d_in[1];   // [512, 4096]
    const float* Wh   = (const float*)d_in[2];   // [1024, 4096]
    const float* bias = (const float*)d_in[3];   // [4096]
    float* out = (float*)d_out;                  // [64, 512, 1024]

    float* P;
    cudaGetSymbolAddress((void**)&P, g_P);

    const int smem_bytes = (32768 + 64 * 68 + 64 * 33) * sizeof(float); // 156,928
    cudaFuncSetAttribute(lstm_persist_kernel,
                         cudaFuncAttributeMaxDynamicSharedMemorySize, smem_bytes);

    init_kernel<<<(Bv * Uv + 255) / 256, 256>>>();

    dim3 xgrid(Gv / 64, (Tv * Bv) / 64);
    xproj_kernel<<<xgrid, 256>>>(x, Wx, bias, P);

    lstm_persist_kernel<<<NBLK, 256, smem_bytes>>>(Wh, out);
}

// round 5
// speedup vs baseline: 3.0761x; 3.0761x over previous
#include <cuda_runtime.h>
#include <cuda_bf16.h>
#include <math.h>
#include <stdint.h>

#define Bv 64
#define Tv 512
#define Dv 512
#define Uv 1024
#define Gv 4096   // 4*U

// ---------------------------------------------------------------------------
// Scratch (static device allocations are the sanctioned scratch mechanism)
// ---------------------------------------------------------------------------
__device__ float          g_P[(size_t)Tv * Bv * Gv];     // 512 MiB x-projection [t][b][4U]
__device__ __nv_bfloat16  g_Wt_hi[(size_t)Gv * Uv];      // permuted/transposed Wh, hi part
__device__ __nv_bfloat16  g_Wt_lo[(size_t)Gv * Uv];      // lo part
__device__ __nv_bfloat16  g_h_hi[2][Bv * Uv];            // hidden state hi (double buffered)
__device__ __nv_bfloat16  g_h_lo[2][Bv * Uv];            // hidden state lo
__device__ float          g_c[Bv * Uv];                  // cell state fp32

// ---------------------------------------------------------------------------
// helpers
// ---------------------------------------------------------------------------
__device__ __forceinline__ uint32_t smem_to_u32(const void* p) {
    uint32_t a;
    asm("{ .reg .u64 t; cvta.to.shared.u64 t, %1; cvt.u32.u64 %0, t; }" : "=r"(a) : "l"(p));
    return a;
}

__device__ __forceinline__ void ldsm_x4(uint32_t& r0, uint32_t& r1, uint32_t& r2,
                                        uint32_t& r3, uint32_t addr) {
    asm volatile("ldmatrix.sync.aligned.m8n8.x4.shared.b16 {%0,%1,%2,%3}, [%4];"
                 : "=r"(r0), "=r"(r1), "=r"(r2), "=r"(r3) : "r"(addr));
}

__device__ __forceinline__ void mma_bf16(float* d, uint32_t a0, uint32_t a1,
                                         uint32_t a2, uint32_t a3,
                                         uint32_t b0, uint32_t b1) {
    asm volatile(
        "mma.sync.aligned.m16n8k16.row.col.f32.bf16.bf16.f32 "
        "{%0,%1,%2,%3}, {%4,%5,%6,%7}, {%8,%9}, {%0,%1,%2,%3};"
        : "+f"(d[0]), "+f"(d[1]), "+f"(d[2]), "+f"(d[3])
        : "r"(a0), "r"(a1), "r"(a2), "r"(a3), "r"(b0), "r"(b1));
}

// swizzled byte offset within a tile with 256B rows (128 bf16 per row)
__device__ __forceinline__ uint32_t swz(int row, int colb) {
    return (uint32_t)(row * 256 + (colb ^ ((row & 7) << 4)));
}

// ---------------------------------------------------------------------------
// init: zero h(buf0) hi/lo and c
// ---------------------------------------------------------------------------
__global__ void init_kernel() {
    int i = blockIdx.x * blockDim.x + threadIdx.x;
    if (i < Bv * Uv) {
        g_h_hi[0][i] = __float2bfloat16(0.0f);
        g_h_lo[0][i] = __float2bfloat16(0.0f);
        g_c[i]       = 0.0f;
    }
}

// ---------------------------------------------------------------------------
// prep_w: permuted+transposed split-bf16 recurrent weights, K-major rows.
// Row r = blk*32 + g*8 + j  (CTA blk owns units [blk*8, blk*8+8)), col k:
//   Wt[r][k] = Wh[k][g*1024 + blk*8 + j]
// ---------------------------------------------------------------------------
__global__ __launch_bounds__(256) void prep_w_kernel(const float* __restrict__ Wh) {
    size_t o = (size_t)blockIdx.x * 256 + threadIdx.x;   // < 4096*1024
    int r = (int)(o >> 10);
    int k = (int)(o & 1023);
    int blk = r >> 5;
    int rr  = r & 31;
    int g   = rr >> 3;
    int j   = rr & 7;
    int n   = g * Uv + blk * 8 + j;
    float w = Wh[(size_t)k * Gv + n];
    __nv_bfloat16 hi = __float2bfloat16(w);
    float lo = w - __bfloat162float(hi);
    g_Wt_hi[o] = hi;
    g_Wt_lo[o] = __float2bfloat16(lo);
}

// ---------------------------------------------------------------------------
// x-projection GEMM (fp32 SIMT): P[t*64+b][n] = x[b][t][:] . Wx[:][n] + b[n]
// ---------------------------------------------------------------------------
__global__ __launch_bounds__(256) void xproj_kernel(
    const float* __restrict__ x,
    const float* __restrict__ Wx,
    const float* __restrict__ bias,
    float* __restrict__ P)
{
    __shared__ float As[16][65];
    __shared__ float Bs[16][64];

    int tid = threadIdx.x;
    int n0  = blockIdx.x * 64;
    int m0  = blockIdx.y * 64;
    int t   = m0 >> 6;

    int a_row = tid >> 2;
    int a_c   = (tid & 3) * 4;
    const float* xrow = x + (size_t)a_row * Tv * Dv + (size_t)t * Dv;

    int b_row = tid >> 4;
    int b_c   = (tid & 15) * 4;

    int tx = tid & 15;
    int ty = tid >> 4;

    float acc[4][4];
#pragma unroll
    for (int i = 0; i < 4; i++)
#pragma unroll
        for (int j = 0; j < 4; j++) acc[i][j] = 0.0f;

    for (int kc = 0; kc < Dv; kc += 16) {
        float4 av = *(const float4*)(xrow + kc + a_c);
        As[a_c + 0][a_row] = av.x;
        As[a_c + 1][a_row] = av.y;
        As[a_c + 2][a_row] = av.z;
        As[a_c + 3][a_row] = av.w;
        float4 bv = *(const float4*)(Wx + (size_t)(kc + b_row) * Gv + n0 + b_c);
        *(float4*)&Bs[b_row][b_c] = bv;
        __syncthreads();

#pragma unroll
        for (int k = 0; k < 16; k++) {
            float a0 = As[k][ty * 4 + 0];
            float a1 = As[k][ty * 4 + 1];
            float a2 = As[k][ty * 4 + 2];
            float a3 = As[k][ty * 4 + 3];
            float4 b4 = *(const float4*)&Bs[k][tx * 4];
            acc[0][0] += a0 * b4.x; acc[0][1] += a0 * b4.y; acc[0][2] += a0 * b4.z; acc[0][3] += a0 * b4.w;
            acc[1][0] += a1 * b4.x; acc[1][1] += a1 * b4.y; acc[1][2] += a1 * b4.z; acc[1][3] += a1 * b4.w;
            acc[2][0] += a2 * b4.x; acc[2][1] += a2 * b4.y; acc[2][2] += a2 * b4.z; acc[2][3] += a2 * b4.w;
            acc[3][0] += a3 * b4.x; acc[3][1] += a3 * b4.y; acc[3][2] += a3 * b4.z; acc[3][3] += a3 * b4.w;
        }
        __syncthreads();
    }

    float4 bb = *(const float4*)(bias + n0 + tx * 4);
#pragma unroll
    for (int i = 0; i < 4; i++) {
        float4 o;
        o.x = acc[i][0] + bb.x;
        o.y = acc[i][1] + bb.y;
        o.z = acc[i][2] + bb.z;
        o.w = acc[i][3] + bb.w;
        *(float4*)(P + (size_t)(m0 + ty * 4 + i) * Gv + n0 + tx * 4) = o;
    }
}

// ---------------------------------------------------------------------------
// mma.sync LSTM step. 128 CTAs x 256 threads (8 warps).
// CTA blk: D[64 x 32] = h[64x1024] . Wt_slice^T  (3-term bf16 split, fp32 acc)
// then fused LSTM pointwise for units [blk*8, blk*8+8).
//
// Dynamic SMEM: hs_hi 16KB | hs_lo 16KB | ws_hi 8KB | ws_lo 8KB = 48 KB.
// gs (64x33 fp32) overlays hs_hi in the epilogue.
// ---------------------------------------------------------------------------
#define KC    128          // K chunk
#define NCH   8            // 1024 / 128
#define OFF_HHI 0
#define OFF_HLO 16384
#define OFF_WHI 32768
#define OFF_WLO 40960
#define STEP_SMEM 49152

__global__ __launch_bounds__(256) void lstm_step_mma(float* __restrict__ out, int t)
{
    extern __shared__ __align__(256) char smem[];
    uint32_t sbase = smem_to_u32(smem);

    const int tid  = threadIdx.x;
    const int wid  = tid >> 5;
    const int lane = tid & 31;
    const int blk  = blockIdx.x;

    const __nv_bfloat16* W_hi = g_Wt_hi + (size_t)blk * 32 * Uv;
    const __nv_bfloat16* W_lo = g_Wt_lo + (size_t)blk * 32 * Uv;
    const __nv_bfloat16* H_hi = g_h_hi[t & 1];
    const __nv_bfloat16* H_lo = g_h_lo[t & 1];

    // warp tile: m-tile (16 batches), n16-group (16 cols)
    const int m0 = (wid & 3) * 16;
    const int n0 = (wid >> 2) * 16;

    // ldmatrix source addresses (lane-dependent row/col pattern)
    // A (h): lanes: row = m0 + (l&15), colb += (l>>4)*16
    const int a_row = m0 + (lane & 15);
    const int a_cb  = (lane >> 4) * 16;
    // B (Wt): row = n0 + (l>=16)*8 + (l&7), colb += ((l>>3)&1)*16
    const int b_row = n0 + ((lane >> 4) << 3) + (lane & 7);
    const int b_cb  = ((lane >> 3) & 1) * 16;

    float d[2][4];
#pragma unroll
    for (int i = 0; i < 2; i++)
#pragma unroll
        for (int j = 0; j < 4; j++) d[i][j] = 0.0f;

    // staging prefetch registers
    uint4 ph_hi[4], ph_lo[4], pw_hi[2], pw_lo[2];

#define LDG_CHUNK(kc)                                                           \
    {                                                                           \
        _Pragma("unroll")                                                       \
        for (int i = 0; i < 4; i++) {                                           \
            int idx = tid + i * 256;          /* [0,1024) */                    \
            int r = idx >> 4, q = idx & 15;                                     \
            ph_hi[i] = *(const uint4*)(H_hi + (size_t)r * Uv + (kc) + q * 8);   \
            ph_lo[i] = *(const uint4*)(H_lo + (size_t)r * Uv + (kc) + q * 8);   \
        }                                                                       \
        _Pragma("unroll")                                                       \
        for (int i = 0; i < 2; i++) {                                           \
            int idx = tid + i * 256;          /* [0,512) */                     \
            int r = idx >> 4, q = idx & 15;                                     \
            pw_hi[i] = *(const uint4*)(W_hi + (size_t)r * Uv + (kc) + q * 8);   \
            pw_lo[i] = *(const uint4*)(W_lo + (size_t)r * Uv + (kc) + q * 8);   \
        }                                                                       \
    }

    LDG_CHUNK(0);

    for (int c = 0; c < NCH; c++) {
        // commit prefetched chunk to swizzled SMEM
#pragma unroll
        for (int i = 0; i < 4; i++) {
            int idx = tid + i * 256;
            int r = idx >> 4, q = idx & 15;
            uint32_t off = swz(r, q * 16);
            *(uint4*)(smem + OFF_HHI + off) = ph_hi[i];
            *(uint4*)(smem + OFF_HLO + off) = ph_lo[i];
        }
#pragma unroll
        for (int i = 0; i < 2; i++) {
            int idx = tid + i * 256;
            int r = idx >> 4, q = idx & 15;
            uint32_t off = swz(r, q * 16);
            *(uint4*)(smem + OFF_WHI + off) = pw_hi[i];
            *(uint4*)(smem + OFF_WLO + off) = pw_lo[i];
        }
        __syncthreads();

        if (c + 1 < NCH) LDG_CHUNK((c + 1) * KC);

#pragma unroll
        for (int ks = 0; ks < KC / 16; ks++) {
            uint32_t ah0, ah1, ah2, ah3, al0, al1, al2, al3;
            uint32_t bh0, bh1, bh2, bh3, bl0, bl1, bl2, bl3;
            uint32_t a_off = swz(a_row, ks * 32 + a_cb);
            uint32_t b_off = swz(b_row, ks * 32 + b_cb);
            ldsm_x4(ah0, ah1, ah2, ah3, sbase + OFF_HHI + a_off);
            ldsm_x4(al0, al1, al2, al3, sbase + OFF_HLO + a_off);
            ldsm_x4(bh0, bh1, bh2, bh3, sbase + OFF_WHI + b_off);
            ldsm_x4(bl0, bl1, bl2, bl3, sbase + OFF_WLO + b_off);

            // 3-term split: hi*hi + hi*lo + lo*hi
            mma_bf16(d[0], ah0, ah1, ah2, ah3, bh0, bh1);
            mma_bf16(d[1], ah0, ah1, ah2, ah3, bh2, bh3);
            mma_bf16(d[0], ah0, ah1, ah2, ah3, bl0, bl1);
            mma_bf16(d[1], ah0, ah1, ah2, ah3, bl2, bl3);
            mma_bf16(d[0], al0, al1, al2, al3, bh0, bh1);
            mma_bf16(d[1], al0, al1, al2, al3, bh2, bh3);
        }
        __syncthreads();
    }

    // park gates in SMEM (overlay hs_hi): gs[b][lc], lc = g*8 + j, pad 33
    float* gs = (float*)(smem + OFF_HHI);
    {
        int row0 = m0 + (lane >> 2);
        int col0 = (lane & 3) * 2;
#pragma unroll
        for (int nn = 0; nn < 2; nn++) {
            int cc = n0 + nn * 8 + col0;
            gs[row0 * 33 + cc]           = d[nn][0];
            gs[row0 * 33 + cc + 1]       = d[nn][1];
            gs[(row0 + 8) * 33 + cc]     = d[nn][2];
            gs[(row0 + 8) * 33 + cc + 1] = d[nn][3];
        }
    }
    __syncthreads();

    // fused LSTM pointwise: 64 batches x 8 units = 512 pairs, 2 per thread
    const float* Pt = g_P + (size_t)t * Bv * Gv;
    __nv_bfloat16* nh_hi = g_h_hi[(t + 1) & 1];
    __nv_bfloat16* nh_lo = g_h_lo[(t + 1) & 1];
#pragma unroll
    for (int i = 0; i < 2; i++) {
        int p = tid + i * 256;
        int b = p >> 3;
        int j = p & 7;
        int u = blk * 8 + j;
        const float* Pb = Pt + (size_t)b * Gv;

        float xi = gs[b * 33 + 0 * 8 + j] + Pb[u];
        float xf = gs[b * 33 + 1 * 8 + j] + Pb[Uv + u];
        float xg = gs[b * 33 + 2 * 8 + j] + Pb[2 * Uv + u];
        float xo = gs[b * 33 + 3 * 8 + j] + Pb[3 * Uv + u];

        float ig = 1.0f / (1.0f + expf(-xi));
        float fg = 1.0f / (1.0f + expf(-xf));
        float gg = tanhf(xg);
        float og = 1.0f / (1.0f + expf(-xo));

        int idx = b * Uv + u;
        float cc = fg * g_c[idx] + ig * gg;
        g_c[idx] = cc;
        float h = og * tanhf(cc);

        out[((size_t)b * Tv + t) * Uv + u] = h;
        __nv_bfloat16 hh = __float2bfloat16(h);
        nh_hi[idx] = hh;
        nh_lo[idx] = __float2bfloat16(h - __bfloat162float(hh));
    }
}

// ---------------------------------------------------------------------------
// Launch: init -> prep_w -> xproj -> 512 x mma.sync step
// ---------------------------------------------------------------------------
extern "C" void kernel_launch(void* const* d_in, const int* in_sizes, int n_in,
                              void* d_out, int out_size)
{
    const float* x    = (const float*)d_in[0];   // [64, 512, 512]
    const float* Wx   = (const float*)d_in[1];   // [512, 4096]
    const float* Wh   = (const float*)d_in[2];   // [1024, 4096]
    const float* bias = (const float*)d_in[3];   // [4096]
    float* out = (float*)d_out;                  // [64, 512, 1024]

    float* P;
    cudaGetSymbolAddress((void**)&P, g_P);

    static int configured = 0;
    if (!configured) {
        cudaFuncSetAttribute(lstm_step_mma,
                             cudaFuncAttributeMaxDynamicSharedMemorySize, STEP_SMEM);
        configured = 1;
    }

    init_kernel<<<(Bv * Uv + 255) / 256, 256>>>();
    prep_w_kernel<<<(Gv * Uv) / 256, 256>>>(Wh);

    dim3 xgrid(Gv / 64, (Tv * Bv) / 64);
    xproj_kernel<<<xgrid, 256>>>(x, Wx, bias, P);

    for (int t = 0; t < Tv; t++) {
        lstm_step_mma<<<128, 256, STEP_SMEM>>>(out, t);
    }
}

// round 9
// speedup vs baseline: 4.8847x; 1.5880x over previous
#include <cuda_runtime.h>
#include <cuda_bf16.h>
#include <math.h>
#include <stdint.h>

#define Bv 64
#define Tv 512
#define Dv 512
#define Uv 1024
#define Gv 4096   // 4*U
#define Kc 1536   // combined K = U + D

// ---------------------------------------------------------------------------
// Scratch (static device allocations are the sanctioned scratch mechanism)
// ---------------------------------------------------------------------------
__device__ __nv_bfloat16  g_W_hi[(size_t)Gv * Kc];       // permuted [Wh;Wx]^T, hi
__device__ __nv_bfloat16  g_W_lo[(size_t)Gv * Kc];       // lo
__device__ __nv_bfloat16  g_xs_hi[(size_t)Tv * Bv * Dv]; // x transposed [t][b][d], hi
__device__ __nv_bfloat16  g_xs_lo[(size_t)Tv * Bv * Dv]; // lo
__device__ __nv_bfloat16  g_h_hi[2][Bv * Uv];            // hidden state hi (dbl buf)
__device__ __nv_bfloat16  g_h_lo[2][Bv * Uv];            // lo
__device__ float          g_c[Bv * Uv];                  // cell state fp32

// ---------------------------------------------------------------------------
// helpers
// ---------------------------------------------------------------------------
__device__ __forceinline__ uint32_t smem_to_u32(const void* p) {
    uint32_t a;
    asm("{ .reg .u64 t; cvta.to.shared.u64 t, %1; cvt.u32.u64 %0, t; }" : "=r"(a) : "l"(p));
    return a;
}
__device__ __forceinline__ void ldsm_x4(uint32_t& r0, uint32_t& r1, uint32_t& r2,
                                        uint32_t& r3, uint32_t addr) {
    asm volatile("ldmatrix.sync.aligned.m8n8.x4.shared.b16 {%0,%1,%2,%3}, [%4];"
                 : "=r"(r0), "=r"(r1), "=r"(r2), "=r"(r3) : "r"(addr));
}
__device__ __forceinline__ void mma_bf16(float* d, uint32_t a0, uint32_t a1,
                                         uint32_t a2, uint32_t a3,
                                         uint32_t b0, uint32_t b1) {
    asm volatile(
        "mma.sync.aligned.m16n8k16.row.col.f32.bf16.bf16.f32 "
        "{%0,%1,%2,%3}, {%4,%5,%6,%7}, {%8,%9}, {%0,%1,%2,%3};"
        : "+f"(d[0]), "+f"(d[1]), "+f"(d[2]), "+f"(d[3])
        : "r"(a0), "r"(a1), "r"(a2), "r"(a3), "r"(b0), "r"(b1));
}
__device__ __forceinline__ void cp16(uint32_t saddr, const void* g) {
    asm volatile("cp.async.cg.shared.global [%0], [%1], 16;" :: "r"(saddr), "l"(g));
}
#define CP_COMMIT() asm volatile("cp.async.commit_group;" ::: "memory")
#define CP_WAIT2()  asm volatile("cp.async.wait_group 2;" ::: "memory")

// swizzled byte offset within a tile with 256B rows (128 bf16 per row)
__device__ __forceinline__ uint32_t swz(int row, int colb) {
    return (uint32_t)(row * 256 + (colb ^ ((row & 7) << 4)));
}

// ---------------------------------------------------------------------------
// init: zero h(buf0) hi/lo and c
// ---------------------------------------------------------------------------
__global__ void init_kernel() {
    int i = blockIdx.x * blockDim.x + threadIdx.x;
    if (i < Bv * Uv) {
        g_h_hi[0][i] = __float2bfloat16(0.0f);
        g_h_lo[0][i] = __float2bfloat16(0.0f);
        g_c[i]       = 0.0f;
    }
}

// ---------------------------------------------------------------------------
// prep_w: permuted combined split-bf16 weights, K-major rows [4096][1536].
// Row r = blk*32 + g*8 + j  ->  n = g*1024 + blk*8 + j.
// col k: k<1024 -> Wh[k][n];  k>=1024 -> Wx[k-1024][n].
// Block tile: 32 rows (one blk) x 128 k. Reads sector-coalesced via the
// j-runs of 8 consecutive n; writes coalesced in k.
// ---------------------------------------------------------------------------
__global__ __launch_bounds__(256) void prep_w_kernel(
    const float* __restrict__ Wh, const float* __restrict__ Wx)
{
    __shared__ float tile[32][128];
    int tid = threadIdx.x;
    int k0  = blockIdx.x * 128;
    int blk = blockIdx.y;          // 0..127

    // read: t%32 -> local n (g*8+j), t/32 -> k sub (8 per pass, 16 passes)
    int nl = tid & 31;             // g*8 + j
    int g  = nl >> 3;
    int j  = nl & 7;
    int n  = g * Uv + blk * 8 + j;
#pragma unroll 4
    for (int pass = 0; pass < 16; pass++) {
        int k = k0 + (tid >> 5) + pass * 8;
        float w = (k < Uv) ? Wh[(size_t)k * Gv + n]
                           : Wx[(size_t)(k - Uv) * Gv + n];
        tile[nl][(tid >> 5) + pass * 8] = w;   // tile[r_local][k_local]
    }
    __syncthreads();

    // write: 32 rows x 16 16B-units = 512 units, 2 per thread
#pragma unroll
    for (int i = 0; i < 2; i++) {
        int idx = tid + i * 256;
        int rl = idx >> 4;
        int q  = idx & 15;
        __nv_bfloat16 hi8[8], lo8[8];
#pragma unroll
        for (int e = 0; e < 8; e++) {
            float w = tile[rl][q * 8 + e];
            __nv_bfloat16 hi = __float2bfloat16(w);
            hi8[e] = hi;
            lo8[e] = __float2bfloat16(w - __bfloat162float(hi));
        }
        size_t o = (size_t)(blk * 32 + rl) * Kc + k0 + q * 8;
        *(uint4*)(g_W_hi + o) = *(uint4*)hi8;
        *(uint4*)(g_W_lo + o) = *(uint4*)lo8;
    }
}

// ---------------------------------------------------------------------------
// prep_x: x[b][t][d] (fp32) -> xs[t][b][d] split bf16. Both sides coalesced.
// grid: (Tv, Bv), 128 threads, 4 d-elems each.
// ---------------------------------------------------------------------------
__global__ __launch_bounds__(128) void prep_x_kernel(const float* __restrict__ x) {
    int t = blockIdx.x, b = blockIdx.y;
    const float* src = x + ((size_t)b * Tv + t) * Dv;
    size_t dst = ((size_t)t * Bv + b) * Dv;
#pragma unroll
    for (int i = 0; i < 4; i++) {
        int d = threadIdx.x + i * 128;
        float v = src[d];
        __nv_bfloat16 hi = __float2bfloat16(v);
        g_xs_hi[dst + d] = hi;
        g_xs_lo[dst + d] = __float2bfloat16(v - __bfloat162float(hi));
    }
}

// ---------------------------------------------------------------------------
// mma.sync LSTM step, cp.async 4-stage pipeline. 128 CTAs x 256 threads.
// CTA blk: D[64 x 32] = [h | x_t][64x1536] . Wc_slice^T (3-term bf16 split)
// then fused LSTM pointwise (bias added here) for units [blk*8, blk*8+8).
//
// Stage (48 KB): A_hi 16K | A_lo 16K | B_hi 8K | B_lo 8K.  4 stages = 192 KB.
// gs (64x33 fp32) overlays stage 0 in the epilogue.
// ---------------------------------------------------------------------------
#define KC      128
#define NCH     12          // 1536 / 128  (chunks 0..7 = h, 8..11 = x_t)
#define STG     4
#define ST_AHI  0
#define ST_ALO  16384
#define ST_BHI  32768
#define ST_BLO  40960
#define ST_SZ   49152
#define STEP_SMEM (STG * ST_SZ)   // 196608

__global__ __launch_bounds__(256) void lstm_step_mma(float* __restrict__ out,
                                                     const float* __restrict__ bias,
                                                     int t)
{
    extern __shared__ __align__(1024) char smem[];
    uint32_t sbase = smem_to_u32(smem);

    const int tid  = threadIdx.x;
    const int wid  = tid >> 5;
    const int lane = tid & 31;
    const int blk  = blockIdx.x;

    const __nv_bfloat16* W_hi = g_W_hi + (size_t)blk * 32 * Kc;
    const __nv_bfloat16* W_lo = g_W_lo + (size_t)blk * 32 * Kc;
    const __nv_bfloat16* H_hi = g_h_hi[t & 1];
    const __nv_bfloat16* H_lo = g_h_lo[t & 1];
    const __nv_bfloat16* X_hi = g_xs_hi + (size_t)t * Bv * Dv;
    const __nv_bfloat16* X_lo = g_xs_lo + (size_t)t * Bv * Dv;

    // precomputed per-thread load coords
    const int la_r = tid >> 4;          // A row for i=0 (0..15), +16 per i
    const int la_q = tid & 15;          // 16B unit

    // issue one chunk's cp.async into its stage
#define ISSUE(c)                                                                \
    {                                                                           \
        uint32_t st = sbase + ((c) & 3) * ST_SZ;                                \
        const __nv_bfloat16 *ah, *al;                                           \
        int stride, co;                                                         \
        if ((c) < 8) { ah = H_hi; al = H_lo; stride = Uv; co = (c) * KC; }      \
        else         { ah = X_hi; al = X_lo; stride = Dv; co = ((c) - 8) * KC; }\
        _Pragma("unroll")                                                       \
        for (int i = 0; i < 4; i++) {                                           \
            int r = la_r + i * 16;                                              \
            uint32_t off = swz(r, la_q * 16);                                   \
            const __nv_bfloat16* gp = ah + (size_t)r * stride + co + la_q * 8;  \
            const __nv_bfloat16* gq = al + (size_t)r * stride + co + la_q * 8;  \
            cp16(st + ST_AHI + off, gp);                                        \
            cp16(st + ST_ALO + off, gq);                                        \
        }                                                                       \
        _Pragma("unroll")                                                       \
        for (int i = 0; i < 2; i++) {                                           \
            int r = la_r + i * 16;                                              \
            uint32_t off = swz(r, la_q * 16);                                   \
            cp16(st + ST_BHI + off, W_hi + (size_t)r * Kc + (c) * KC + la_q * 8); \
            cp16(st + ST_BLO + off, W_lo + (size_t)r * Kc + (c) * KC + la_q * 8); \
        }                                                                       \
        CP_COMMIT();                                                            \
    }

    // warp tile: m-tile (16 batches), n16-group (16 cols)
    const int m0 = (wid & 3) * 16;
    const int n0 = (wid >> 2) * 16;
    const int a_row = m0 + (lane & 15);
    const int a_cb  = (lane >> 4) * 16;
    const int b_row = n0 + ((lane >> 4) << 3) + (lane & 7);
    const int b_cb  = ((lane >> 3) & 1) * 16;

    float d[2][4];
#pragma unroll
    for (int i = 0; i < 2; i++)
#pragma unroll
        for (int j = 0; j < 4; j++) d[i][j] = 0.0f;

    ISSUE(0); ISSUE(1); ISSUE(2);

    for (int c = 0; c < NCH; c++) {
        CP_WAIT2();
        __syncthreads();
        if (c + 3 < NCH) { ISSUE(c + 3); } else { CP_COMMIT(); }

        uint32_t stb = sbase + (c & 3) * ST_SZ;
#pragma unroll
        for (int ks = 0; ks < KC / 16; ks++) {
            uint32_t ah0, ah1, ah2, ah3, al0, al1, al2, al3;
            uint32_t bh0, bh1, bh2, bh3, bl0, bl1, bl2, bl3;
            uint32_t a_off = swz(a_row, ks * 32 + a_cb);
            uint32_t b_off = swz(b_row, ks * 32 + b_cb);
            ldsm_x4(ah0, ah1, ah2, ah3, stb + ST_AHI + a_off);
            ldsm_x4(al0, al1, al2, al3, stb + ST_ALO + a_off);
            ldsm_x4(bh0, bh1, bh2, bh3, stb + ST_BHI + b_off);
            ldsm_x4(bl0, bl1, bl2, bl3, stb + ST_BLO + b_off);

            mma_bf16(d[0], ah0, ah1, ah2, ah3, bh0, bh1);
            mma_bf16(d[1], ah0, ah1, ah2, ah3, bh2, bh3);
            mma_bf16(d[0], ah0, ah1, ah2, ah3, bl0, bl1);
            mma_bf16(d[1], ah0, ah1, ah2, ah3, bl2, bl3);
            mma_bf16(d[0], al0, al1, al2, al3, bh0, bh1);
            mma_bf16(d[1], al0, al1, al2, al3, bh2, bh3);
        }
    }
    __syncthreads();

    // park gates in SMEM (overlay stage 0): gs[b][lc], lc = g*8 + j, pad 33
    float* gs = (float*)smem;
    {
        int row0 = m0 + (lane >> 2);
        int col0 = (lane & 3) * 2;
#pragma unroll
        for (int nn = 0; nn < 2; nn++) {
            int cc = n0 + nn * 8 + col0;
            gs[row0 * 33 + cc]           = d[nn][0];
            gs[row0 * 33 + cc + 1]       = d[nn][1];
            gs[(row0 + 8) * 33 + cc]     = d[nn][2];
            gs[(row0 + 8) * 33 + cc + 1] = d[nn][3];
        }
    }
    __syncthreads();

    // fused LSTM pointwise: 64 batches x 8 units = 512 pairs, 2 per thread
    __nv_bfloat16* nh_hi = g_h_hi[(t + 1) & 1];
    __nv_bfloat16* nh_lo = g_h_lo[(t + 1) & 1];
#pragma unroll
    for (int i = 0; i < 2; i++) {
        int p = tid + i * 256;
        int b = p >> 3;
        int j = p & 7;
        int u = blk * 8 + j;

        float xi = gs[b * 33 + 0 * 8 + j] + bias[0 * Uv + u];
        float xf = gs[b * 33 + 1 * 8 + j] + bias[1 * Uv + u];
        float xg = gs[b * 33 + 2 * 8 + j] + bias[2 * Uv + u];
        float xo = gs[b * 33 + 3 * 8 + j] + bias[3 * Uv + u];

        float ig = 1.0f / (1.0f + expf(-xi));
        float fg = 1.0f / (1.0f + expf(-xf));
        float gg = tanhf(xg);
        float og = 1.0f / (1.0f + expf(-xo));

        int idx = b * Uv + u;
        float cc = fg * g_c[idx] + ig * gg;
        g_c[idx] = cc;
        float h = og * tanhf(cc);

        out[((size_t)b * Tv + t) * Uv + u] = h;
        __nv_bfloat16 hh = __float2bfloat16(h);
        nh_hi[idx] = hh;
        nh_lo[idx] = __float2bfloat16(h - __bfloat162float(hh));
    }
}

// ---------------------------------------------------------------------------
// Launch: init -> prep_w -> prep_x -> 512 x pipelined mma.sync step
// ---------------------------------------------------------------------------
extern "C" void kernel_launch(void* const* d_in, const int* in_sizes, int n_in,
                              void* d_out, int out_size)
{
    const float* x    = (const float*)d_in[0];   // [64, 512, 512]
    const float* Wx   = (const float*)d_in[1];   // [512, 4096]
    const float* Wh   = (const float*)d_in[2];   // [1024, 4096]
    const float* bias = (const float*)d_in[3];   // [4096]
    float* out = (float*)d_out;                  // [64, 512, 1024]

    static int configured = 0;
    if (!configured) {
        cudaFuncSetAttribute(lstm_step_mma,
                             cudaFuncAttributeMaxDynamicSharedMemorySize, STEP_SMEM);
        configured = 1;
    }

    init_kernel<<<(Bv * Uv + 255) / 256, 256>>>();

    dim3 wgrid(Kc / 128, Gv / 32);
    prep_w_kernel<<<wgrid, 256>>>(Wh, Wx);

    dim3 xgrid(Tv, Bv);
    prep_x_kernel<<<xgrid, 128>>>(x);

    for (int t = 0; t < Tv; t++) {
        lstm_step_mma<<<128, 256, STEP_SMEM>>>(out, bias, t);
    }
}

// round 15
// speedup vs baseline: 5.1314x; 1.0505x over previous
#include <cuda_runtime.h>
#include <cuda_bf16.h>
#include <math.h>
#include <stdint.h>

#define Bv 64
#define Tv 512
#define Dv 512
#define Uv 1024
#define Gv 4096   // 4*U
#define Kc 1536   // combined K = U + D (W layout; step uses k<1024, xproj k>=1024)

// ---------------------------------------------------------------------------
// Scratch (static device allocations are the sanctioned scratch mechanism)
// ---------------------------------------------------------------------------
__device__ float          g_P[(size_t)Tv * Bv * Gv];     // x-proj + bias, PERMUTED cols
__device__ __nv_bfloat16  g_W_hi[(size_t)Gv * Kc];       // permuted [Wh|Wx] rows, K-major, hi
__device__ __nv_bfloat16  g_W_lo[(size_t)Gv * Kc];       // lo
__device__ __nv_bfloat16  g_xs_hi[(size_t)Tv * Bv * Dv]; // x transposed [t][b][d], hi
__device__ __nv_bfloat16  g_xs_lo[(size_t)Tv * Bv * Dv]; // lo
__device__ __nv_bfloat16  g_h_hi[2][Bv * Uv];            // hidden state hi (dbl buf)
__device__ __nv_bfloat16  g_h_lo[2][Bv * Uv];            // lo
__device__ float          g_c[Bv * Uv];                  // cell state fp32

// ---------------------------------------------------------------------------
// helpers
// ---------------------------------------------------------------------------
__device__ __forceinline__ uint32_t smem_to_u32(const void* p) {
    uint32_t a;
    asm("{ .reg .u64 t; cvta.to.shared.u64 t, %1; cvt.u32.u64 %0, t; }" : "=r"(a) : "l"(p));
    return a;
}
__device__ __forceinline__ void ldsm_x4(uint32_t& r0, uint32_t& r1, uint32_t& r2,
                                        uint32_t& r3, uint32_t addr) {
    asm volatile("ldmatrix.sync.aligned.m8n8.x4.shared.b16 {%0,%1,%2,%3}, [%4];"
                 : "=r"(r0), "=r"(r1), "=r"(r2), "=r"(r3) : "r"(addr));
}
__device__ __forceinline__ void mma_bf16(float* d, uint32_t a0, uint32_t a1,
                                         uint32_t a2, uint32_t a3,
                                         uint32_t b0, uint32_t b1) {
    asm volatile(
        "mma.sync.aligned.m16n8k16.row.col.f32.bf16.bf16.f32 "
        "{%0,%1,%2,%3}, {%4,%5,%6,%7}, {%8,%9}, {%0,%1,%2,%3};"
        : "+f"(d[0]), "+f"(d[1]), "+f"(d[2]), "+f"(d[3])
        : "r"(a0), "r"(a1), "r"(a2), "r"(a3), "r"(b0), "r"(b1));
}
__device__ __forceinline__ void cp16(uint32_t saddr, const void* g) {
    asm volatile("cp.async.cg.shared.global [%0], [%1], 16;" :: "r"(saddr), "l"(g));
}
#define CP_COMMIT() asm volatile("cp.async.commit_group;" ::: "memory")
#define CP_WAIT2()  asm volatile("cp.async.wait_group 2;" ::: "memory")
#define CP_WAIT1()  asm volatile("cp.async.wait_group 1;" ::: "memory")
#define CP_WAIT0()  asm volatile("cp.async.wait_group 0;" ::: "memory")

// swizzled byte offset within a tile with 256B rows (128 bf16 per row)
__device__ __forceinline__ uint32_t swz(int row, int colb) {
    return (uint32_t)(row * 256 + (colb ^ ((row & 7) << 4)));
}

// ---------------------------------------------------------------------------
// init: zero h(buf0) hi/lo and c
// ---------------------------------------------------------------------------
__global__ void init_kernel() {
    int i = blockIdx.x * blockDim.x + threadIdx.x;
    if (i < Bv * Uv) {
        g_h_hi[0][i] = __float2bfloat16(0.0f);
        g_h_lo[0][i] = __float2bfloat16(0.0f);
        g_c[i]       = 0.0f;
    }
}

// ---------------------------------------------------------------------------
// prep_w: permuted combined split-bf16 weights, K-major rows [4096][1536].
// Row r = blk*32 + g*8 + j  ->  n = g*1024 + blk*8 + j.
// col k: k<1024 -> Wh[k][n];  k>=1024 -> Wx[k-1024][n].
// ---------------------------------------------------------------------------
__global__ __launch_bounds__(256) void prep_w_kernel(
    const float* __restrict__ Wh, const float* __restrict__ Wx)
{
    __shared__ float tile[32][128];
    int tid = threadIdx.x;
    int k0  = blockIdx.x * 128;
    int blk = blockIdx.y;          // 0..127

    int nl = tid & 31;             // g*8 + j
    int g  = nl >> 3;
    int j  = nl & 7;
    int n  = g * Uv + blk * 8 + j;
#pragma unroll 4
    for (int pass = 0; pass < 16; pass++) {
        int k = k0 + (tid >> 5) + pass * 8;
        float w = (k < Uv) ? Wh[(size_t)k * Gv + n]
                           : Wx[(size_t)(k - Uv) * Gv + n];
        tile[nl][(tid >> 5) + pass * 8] = w;
    }
    __syncthreads();

#pragma unroll
    for (int i = 0; i < 2; i++) {
        int idx = tid + i * 256;
        int rl = idx >> 4;
        int q  = idx & 15;
        __nv_bfloat16 hi8[8], lo8[8];
#pragma unroll
        for (int e = 0; e < 8; e++) {
            float w = tile[rl][q * 8 + e];
            __nv_bfloat16 hi = __float2bfloat16(w);
            hi8[e] = hi;
            lo8[e] = __float2bfloat16(w - __bfloat162float(hi));
        }
        size_t o = (size_t)(blk * 32 + rl) * Kc + k0 + q * 8;
        *(uint4*)(g_W_hi + o) = *(uint4*)hi8;
        *(uint4*)(g_W_lo + o) = *(uint4*)lo8;
    }
}

// ---------------------------------------------------------------------------
// prep_x: x[b][t][d] (fp32) -> xs[t][b][d] split bf16.
// ---------------------------------------------------------------------------
__global__ __launch_bounds__(128) void prep_x_kernel(const float* __restrict__ x) {
    int t = blockIdx.x, b = blockIdx.y;
    const float* src = x + ((size_t)b * Tv + t) * Dv;
    size_t dst = ((size_t)t * Bv + b) * Dv;
#pragma unroll
    for (int i = 0; i < 4; i++) {
        int d = threadIdx.x + i * 128;
        float v = src[d];
        __nv_bfloat16 hi = __float2bfloat16(v);
        g_xs_hi[dst + d] = hi;
        g_xs_lo[dst + d] = __float2bfloat16(v - __bfloat162float(hi));
    }
}

// ---------------------------------------------------------------------------
// xproj_mma: P[m][r] = xs[m][:] . W[r][1024:1536]^T + bias (permuted cols),
// 3-term bf16 split. Tile 128m x 64n, K=512 in 4 chunks, 2-stage cp.async.
// grid (64 n-tiles, 256 m-tiles), 256 threads.
// ---------------------------------------------------------------------------
#define XKC    128
#define XNCH   4
#define XA_HI  0
#define XA_LO  32768
#define XB_HI  65536
#define XB_LO  81920
#define XST_SZ 98304
#define XPROJ_SMEM (2 * XST_SZ)   // 196608

__global__ __launch_bounds__(256) void xproj_mma(const float* __restrict__ bias)
{
    extern __shared__ __align__(1024) char smem[];
    uint32_t sbase = smem_to_u32(smem);

    const int tid  = threadIdx.x;
    const int wid  = tid >> 5;
    const int lane = tid & 31;
    const int nt   = blockIdx.x;
    const int mt   = blockIdx.y;

    const __nv_bfloat16* A_hi = g_xs_hi + (size_t)mt * 128 * Dv;
    const __nv_bfloat16* A_lo = g_xs_lo + (size_t)mt * 128 * Dv;
    const __nv_bfloat16* B_hi = g_W_hi + (size_t)(nt * 64) * Kc + Uv;
    const __nv_bfloat16* B_lo = g_W_lo + (size_t)(nt * 64) * Kc + Uv;

    const int la_r = tid >> 4;     // 0..15
    const int la_q = tid & 15;

#define ISSUE_X(c)                                                              \
    {                                                                           \
        uint32_t st = sbase + ((c) & 1) * XST_SZ;                               \
        _Pragma("unroll")                                                       \
        for (int i = 0; i < 8; i++) {                                           \
            int r = la_r + i * 16;                                              \
            uint32_t off = swz(r, la_q * 16);                                   \
            cp16(st + XA_HI + off, A_hi + (size_t)r * Dv + (c) * XKC + la_q * 8); \
            cp16(st + XA_LO + off, A_lo + (size_t)r * Dv + (c) * XKC + la_q * 8); \
        }                                                                       \
        _Pragma("unroll")                                                       \
        for (int i = 0; i < 4; i++) {                                           \
            int r = la_r + i * 16;                                              \
            uint32_t off = swz(r, la_q * 16);                                   \
            cp16(st + XB_HI + off, B_hi + (size_t)r * Kc + (c) * XKC + la_q * 8); \
            cp16(st + XB_LO + off, B_lo + (size_t)r * Kc + (c) * XKC + la_q * 8); \
        }                                                                       \
        CP_COMMIT();                                                            \
    }

    // warp tile 32m x 32n: 4 m-groups x 2 n-groups
    const int m0 = (wid >> 1) * 32;
    const int n0 = (wid & 1) * 32;
    const int a_row = m0 + (lane & 15);
    const int a_cb  = (lane >> 4) * 16;
    const int b_row = n0 + ((lane >> 4) << 3) + (lane & 7);
    const int b_cb  = ((lane >> 3) & 1) * 16;

    float d[2][4][4];
#pragma unroll
    for (int i = 0; i < 2; i++)
#pragma unroll
        for (int j = 0; j < 4; j++)
#pragma unroll
            for (int e = 0; e < 4; e++) d[i][j][e] = 0.0f;

    ISSUE_X(0);

    for (int c = 0; c < XNCH; c++) {
        if (c + 1 < XNCH) { ISSUE_X(c + 1); CP_WAIT1(); } else { CP_WAIT0(); }
        __syncthreads();

        uint32_t stb = sbase + (c & 1) * XST_SZ;
#pragma unroll
        for (int ks = 0; ks < XKC / 16; ks++) {
            uint32_t ah[8], al[8], bh[8], bl[8];
            uint32_t ao0 = swz(a_row, ks * 32 + a_cb);
            uint32_t ao1 = swz(a_row + 16, ks * 32 + a_cb);
            uint32_t bo0 = swz(b_row, ks * 32 + b_cb);
            uint32_t bo1 = swz(b_row + 16, ks * 32 + b_cb);
            ldsm_x4(ah[0], ah[1], ah[2], ah[3], stb + XA_HI + ao0);
            ldsm_x4(ah[4], ah[5], ah[6], ah[7], stb + XA_HI + ao1);
            ldsm_x4(al[0], al[1], al[2], al[3], stb + XA_LO + ao0);
            ldsm_x4(al[4], al[5], al[6], al[7], stb + XA_LO + ao1);
            ldsm_x4(bh[0], bh[1], bh[2], bh[3], stb + XB_HI + bo0);
            ldsm_x4(bh[4], bh[5], bh[6], bh[7], stb + XB_HI + bo1);
            ldsm_x4(bl[0], bl[1], bl[2], bl[3], stb + XB_LO + bo0);
            ldsm_x4(bl[4], bl[5], bl[6], bl[7], stb + XB_LO + bo1);

#pragma unroll
            for (int mi = 0; mi < 2; mi++)
#pragma unroll
                for (int ng = 0; ng < 4; ng++)
                    mma_bf16(d[mi][ng], ah[mi*4+0], ah[mi*4+1], ah[mi*4+2], ah[mi*4+3],
                             bh[ng*2], bh[ng*2+1]);
#pragma unroll
            for (int mi = 0; mi < 2; mi++)
#pragma unroll
                for (int ng = 0; ng < 4; ng++)
                    mma_bf16(d[mi][ng], ah[mi*4+0], ah[mi*4+1], ah[mi*4+2], ah[mi*4+3],
                             bl[ng*2], bl[ng*2+1]);
#pragma unroll
            for (int mi = 0; mi < 2; mi++)
#pragma unroll
                for (int ng = 0; ng < 4; ng++)
                    mma_bf16(d[mi][ng], al[mi*4+0], al[mi*4+1], al[mi*4+2], al[mi*4+3],
                             bh[ng*2], bh[ng*2+1]);
        }
        __syncthreads();
    }

    // park to SMEM, then coalesced P write with bias folded in
    float* ps = (float*)smem;   // 128 x 66
#pragma unroll
    for (int mi = 0; mi < 2; mi++) {
        int row0 = m0 + mi * 16 + (lane >> 2);
        int cbase = (lane & 3) * 2;
#pragma unroll
        for (int ng = 0; ng < 4; ng++) {
            int cc = n0 + ng * 8 + cbase;    // FIX R10: n0 was missing
            ps[row0 * 66 + cc]           = d[mi][ng][0];
            ps[row0 * 66 + cc + 1]       = d[mi][ng][1];
            ps[(row0 + 8) * 66 + cc]     = d[mi][ng][2];
            ps[(row0 + 8) * 66 + cc + 1] = d[mi][ng][3];
        }
    }
    __syncthreads();

#pragma unroll
    for (int i = 0; i < 8; i++) {
        int idx = tid + i * 256;
        int row = idx >> 4;
        int c4  = (idx & 15) * 4;
        float4 v;
        float* pp = &ps[row * 66 + c4];
        v.x = pp[0]; v.y = pp[1]; v.z = pp[2]; v.w = pp[3];
        // fold bias (permuted col r -> orig n = g*1024 + blk*8 + j)
        float* ve = &v.x;
#pragma unroll
        for (int e = 0; e < 4; e++) {
            int r = nt * 64 + c4 + e;
            int orig = (((r & 31) >> 3) << 10) + ((r >> 5) << 3) + (r & 7);
            ve[e] += bias[orig];
        }
        size_t mrow = (size_t)mt * 128 + row;
        *(float4*)(g_P + mrow * Gv + nt * 64 + c4) = v;
    }
}

// ---------------------------------------------------------------------------
// mma.sync LSTM step, K=1024, warp-level K-split. 128 CTAs x 256 threads.
// Warps 0-3: m-tiles 0-3, k16 0-3 of each chunk; warps 4-7: same m, k16 4-7.
// Warp tile 16m x 32n -> 4 independent accumulator chains.
// Stage (48 KB): A_hi 16K | A_lo 16K | B_hi 8K | B_lo 8K.  4 stages = 192 KB.
// ---------------------------------------------------------------------------
#define KC      128
#define NCH     8           // 1024 / 128
#define ST_AHI  0
#define ST_ALO  16384
#define ST_BHI  32768
#define ST_BLO  40960
#define ST_SZ   49152
#define STEP_SMEM (4 * ST_SZ)   // 196608

__global__ __launch_bounds__(256) void lstm_step_mma(float* __restrict__ out, int t)
{
    extern __shared__ __align__(1024) char smem[];
    uint32_t sbase = smem_to_u32(smem);

    const int tid  = threadIdx.x;
    const int wid  = tid >> 5;
    const int lane = tid & 31;
    const int blk  = blockIdx.x;

    const __nv_bfloat16* W_hi = g_W_hi + (size_t)blk * 32 * Kc;  // k<1024 = Wh part
    const __nv_bfloat16* W_lo = g_W_lo + (size_t)blk * 32 * Kc;
    const __nv_bfloat16* H_hi = g_h_hi[t & 1];
    const __nv_bfloat16* H_lo = g_h_lo[t & 1];

    const int la_r = tid >> 4;
    const int la_q = tid & 15;

#define ISSUE(c)                                                                \
    {                                                                           \
        uint32_t st = sbase + ((c) & 3) * ST_SZ;                                \
        _Pragma("unroll")                                                       \
        for (int i = 0; i < 4; i++) {                                           \
            int r = la_r + i * 16;                                              \
            uint32_t off = swz(r, la_q * 16);                                   \
            cp16(st + ST_AHI + off, H_hi + (size_t)r * Uv + (c) * KC + la_q * 8); \
            cp16(st + ST_ALO + off, H_lo + (size_t)r * Uv + (c) * KC + la_q * 8); \
        }                                                                       \
        _Pragma("unroll")                                                       \
        for (int i = 0; i < 2; i++) {                                           \
            int r = la_r + i * 16;                                              \
            uint32_t off = swz(r, la_q * 16);                                   \
            cp16(st + ST_BHI + off, W_hi + (size_t)r * Kc + (c) * KC + la_q * 8); \
            cp16(st + ST_BLO + off, W_lo + (size_t)r * Kc + (c) * KC + la_q * 8); \
        }                                                                       \
        CP_COMMIT();                                                            \
    }

    const int m0  = (wid & 3) * 16;
    const int ksh = wid >> 2;                    // k16-half: 0 -> ks 0-3, 1 -> ks 4-7
    const int a_row = m0 + (lane & 15);
    const int a_cb  = (lane >> 4) * 16;
    const int b_row = ((lane >> 4) << 3) + (lane & 7);   // 0..15 within B tile
    const int b_cb  = ((lane >> 3) & 1) * 16;

    float d[4][4];
#pragma unroll
    for (int i = 0; i < 4; i++)
#pragma unroll
        for (int j = 0; j < 4; j++) d[i][j] = 0.0f;

    ISSUE(0); ISSUE(1); ISSUE(2);

    for (int c = 0; c < NCH; c++) {
        CP_WAIT2();
        __syncthreads();
        if (c + 3 < NCH) { ISSUE(c + 3); } else { CP_COMMIT(); }

        uint32_t stb = sbase + (c & 3) * ST_SZ;
#pragma unroll
        for (int ks = 0; ks < 4; ks++) {
            int k16 = ksh * 4 + ks;
            uint32_t ah[4], al[4], bh[8], bl[8];
            uint32_t ao  = swz(a_row, k16 * 32 + a_cb);
            uint32_t bo0 = swz(b_row, k16 * 32 + b_cb);
            uint32_t bo1 = swz(b_row + 16, k16 * 32 + b_cb);
            ldsm_x4(ah[0], ah[1], ah[2], ah[3], stb + ST_AHI + ao);
            ldsm_x4(al[0], al[1], al[2], al[3], stb + ST_ALO + ao);
            ldsm_x4(bh[0], bh[1], bh[2], bh[3], stb + ST_BHI + bo0);
            ldsm_x4(bh[4], bh[5], bh[6], bh[7], stb + ST_BHI + bo1);
            ldsm_x4(bl[0], bl[1], bl[2], bl[3], stb + ST_BLO + bo0);
            ldsm_x4(bl[4], bl[5], bl[6], bl[7], stb + ST_BLO + bo1);

#pragma unroll
            for (int ng = 0; ng < 4; ng++)
                mma_bf16(d[ng], ah[0], ah[1], ah[2], ah[3], bh[ng*2], bh[ng*2+1]);
#pragma unroll
            for (int ng = 0; ng < 4; ng++)
                mma_bf16(d[ng], ah[0], ah[1], ah[2], ah[3], bl[ng*2], bl[ng*2+1]);
#pragma unroll
            for (int ng = 0; ng < 4; ng++)
                mma_bf16(d[ng], al[0], al[1], al[2], al[3], bh[ng*2], bh[ng*2+1]);
        }
    }
    __syncthreads();

    // merge the two ks-halves via SMEM (overlay stage 0)
    float* gsA = (float*)smem;            // [64][33]
    float* gsB = gsA + 64 * 33;
    {
        float* g = ksh ? gsB : gsA;
        int row0 = m0 + (lane >> 2);
        int cbase = (lane & 3) * 2;
#pragma unroll
        for (int ng = 0; ng < 4; ng++) {
            int cc = ng * 8 + cbase;
            g[row0 * 33 + cc]           = d[ng][0];
            g[row0 * 33 + cc + 1]       = d[ng][1];
            g[(row0 + 8) * 33 + cc]     = d[ng][2];
            g[(row0 + 8) * 33 + cc + 1] = d[ng][3];
        }
    }
    __syncthreads();

    // fused LSTM pointwise: 64 batches x 8 units = 512 pairs, 2 per thread
    __nv_bfloat16* nh_hi = g_h_hi[(t + 1) & 1];
    __nv_bfloat16* nh_lo = g_h_lo[(t + 1) & 1];
#pragma unroll
    for (int i = 0; i < 2; i++) {
        int p = tid + i * 256;
        int b = p >> 3;
        int j = p & 7;
        int u = blk * 8 + j;
        const float* Pb = g_P + ((size_t)t * Bv + b) * Gv + blk * 32;

        float xi = gsA[b * 33 + 0 * 8 + j] + gsB[b * 33 + 0 * 8 + j] + Pb[0 * 8 + j];
        float xf = gsA[b * 33 + 1 * 8 + j] + gsB[b * 33 + 1 * 8 + j] + Pb[1 * 8 + j];
        float xg = gsA[b * 33 + 2 * 8 + j] + gsB[b * 33 + 2 * 8 + j] + Pb[2 * 8 + j];
        float xo = gsA[b * 33 + 3 * 8 + j] + gsB[b * 33 + 3 * 8 + j] + Pb[3 * 8 + j];

        float ig = 1.0f / (1.0f + expf(-xi));
        float fg = 1.0f / (1.0f + expf(-xf));
        float gg = tanhf(xg);
        float og = 1.0f / (1.0f + expf(-xo));

        int idx = b * Uv + u;
        float cc = fg * g_c[idx] + ig * gg;
        g_c[idx] = cc;
        float h = og * tanhf(cc);

        out[((size_t)b * Tv + t) * Uv + u] = h;
        __nv_bfloat16 hh = __float2bfloat16(h);
        nh_hi[idx] = hh;
        nh_lo[idx] = __float2bfloat16(h - __bfloat162float(hh));
    }
}

// ---------------------------------------------------------------------------
// Launch: init -> prep_w -> prep_x -> xproj_mma -> 512 x step
// ---------------------------------------------------------------------------
extern "C" void kernel_launch(void* const* d_in, const int* in_sizes, int n_in,
                              void* d_out, int out_size)
{
    const float* x    = (const float*)d_in[0];   // [64, 512, 512]
    const float* Wx   = (const float*)d_in[1];   // [512, 4096]
    const float* Wh   = (const float*)d_in[2];   // [1024, 4096]
    const float* bias = (const float*)d_in[3];   // [4096]
    float* out = (float*)d_out;                  // [64, 512, 1024]

    static int configured = 0;
    if (!configured) {
        cudaFuncSetAttribute(lstm_step_mma,
                             cudaFuncAttributeMaxDynamicSharedMemorySize, STEP_SMEM);
        cudaFuncSetAttribute(xproj_mma,
                             cudaFuncAttributeMaxDynamicSharedMemorySize, XPROJ_SMEM);
        configured = 1;
    }

    init_kernel<<<(Bv * Uv + 255) / 256, 256>>>();

    dim3 wgrid(Kc / 128, Gv / 32);
    prep_w_kernel<<<wgrid, 256>>>(Wh, Wx);

    dim3 xgrid(Tv, Bv);
    prep_x_kernel<<<xgrid, 128>>>(x);

    dim3 pgrid(Gv / 64, (Tv * Bv) / 128);
    xproj_mma<<<pgrid, 256, XPROJ_SMEM>>>(bias);

    for (int t = 0; t < Tv; t++) {
        lstm_step_mma<<<128, 256, STEP_SMEM>>>(out, t);
    }
}

// round 16
// speedup vs baseline: 5.4130x; 1.0549x over previous
#include <cuda_runtime.h>
#include <cuda_bf16.h>
#include <math.h>
#include <stdint.h>

#define Bv 64
#define Tv 512
#define Dv 512
#define Uv 1024
#define Gv 4096   // 4*U
#define Kc 1536   // combined K = U + D (W layout; step uses k<1024, xproj k>=1024)
#define NBLK 128

// ---------------------------------------------------------------------------
// Scratch (static device allocations are the sanctioned scratch mechanism)
// ---------------------------------------------------------------------------
__device__ float          g_P[(size_t)Tv * Bv * Gv];     // x-proj + bias, PERMUTED cols
__device__ __nv_bfloat16  g_W_hi[(size_t)Gv * Kc];       // permuted [Wh|Wx] rows, K-major, hi
__device__ __nv_bfloat16  g_W_lo[(size_t)Gv * Kc];       // lo
__device__ __nv_bfloat16  g_xs_hi[(size_t)Tv * Bv * Dv]; // x transposed [t][b][d], hi
__device__ __nv_bfloat16  g_xs_lo[(size_t)Tv * Bv * Dv]; // lo
__device__ __nv_bfloat16  g_h_hi[2][Bv * Uv];            // hidden state hi (dbl buf)
__device__ __nv_bfloat16  g_h_lo[2][Bv * Uv];            // lo
__device__ float          g_c[Bv * Uv];                  // cell state fp32
__device__ int            g_count;                       // persistent grid barrier

// ---------------------------------------------------------------------------
// helpers
// ---------------------------------------------------------------------------
__device__ __forceinline__ uint32_t smem_to_u32(const void* p) {
    uint32_t a;
    asm("{ .reg .u64 t; cvta.to.shared.u64 t, %1; cvt.u32.u64 %0, t; }" : "=r"(a) : "l"(p));
    return a;
}
__device__ __forceinline__ void ldsm_x4(uint32_t& r0, uint32_t& r1, uint32_t& r2,
                                        uint32_t& r3, uint32_t addr) {
    asm volatile("ldmatrix.sync.aligned.m8n8.x4.shared.b16 {%0,%1,%2,%3}, [%4];"
                 : "=r"(r0), "=r"(r1), "=r"(r2), "=r"(r3) : "r"(addr));
}
__device__ __forceinline__ void mma_bf16(float* d, uint32_t a0, uint32_t a1,
                                         uint32_t a2, uint32_t a3,
                                         uint32_t b0, uint32_t b1) {
    asm volatile(
        "mma.sync.aligned.m16n8k16.row.col.f32.bf16.bf16.f32 "
        "{%0,%1,%2,%3}, {%4,%5,%6,%7}, {%8,%9}, {%0,%1,%2,%3};"
        : "+f"(d[0]), "+f"(d[1]), "+f"(d[2]), "+f"(d[3])
        : "r"(a0), "r"(a1), "r"(a2), "r"(a3), "r"(b0), "r"(b1));
}
__device__ __forceinline__ void cp16(uint32_t saddr, const void* g) {
    asm volatile("cp.async.cg.shared.global [%0], [%1], 16;" :: "r"(saddr), "l"(g));
}
#define CP_COMMIT() asm volatile("cp.async.commit_group;" ::: "memory")
#define CP_WAIT1()  asm volatile("cp.async.wait_group 1;" ::: "memory")
#define CP_WAIT0()  asm volatile("cp.async.wait_group 0;" ::: "memory")

// swizzled byte offset within a tile with 256B rows (128 bf16 per row)
__device__ __forceinline__ uint32_t swz(int row, int colb) {
    return (uint32_t)(row * 256 + (colb ^ ((row & 7) << 4)));
}

// ---------------------------------------------------------------------------
// init: zero h(buf0) hi/lo, c, barrier counter
// ---------------------------------------------------------------------------
__global__ void init_kernel() {
    int i = blockIdx.x * blockDim.x + threadIdx.x;
    if (i < Bv * Uv) {
        g_h_hi[0][i] = __float2bfloat16(0.0f);
        g_h_lo[0][i] = __float2bfloat16(0.0f);
        g_c[i]       = 0.0f;
    }
    if (i == 0) g_count = 0;
}

// ---------------------------------------------------------------------------
// prep_w: permuted combined split-bf16 weights, K-major rows [4096][1536].
// Row r = blk*32 + g*8 + j  ->  n = g*1024 + blk*8 + j.
// col k: k<1024 -> Wh[k][n];  k>=1024 -> Wx[k-1024][n].
// ---------------------------------------------------------------------------
__global__ __launch_bounds__(256) void prep_w_kernel(
    const float* __restrict__ Wh, const float* __restrict__ Wx)
{
    __shared__ float tile[32][128];
    int tid = threadIdx.x;
    int k0  = blockIdx.x * 128;
    int blk = blockIdx.y;          // 0..127

    int nl = tid & 31;             // g*8 + j
    int g  = nl >> 3;
    int j  = nl & 7;
    int n  = g * Uv + blk * 8 + j;
#pragma unroll 4
    for (int pass = 0; pass < 16; pass++) {
        int k = k0 + (tid >> 5) + pass * 8;
        float w = (k < Uv) ? Wh[(size_t)k * Gv + n]
                           : Wx[(size_t)(k - Uv) * Gv + n];
        tile[nl][(tid >> 5) + pass * 8] = w;
    }
    __syncthreads();

#pragma unroll
    for (int i = 0; i < 2; i++) {
        int idx = tid + i * 256;
        int rl = idx >> 4;
        int q  = idx & 15;
        __nv_bfloat16 hi8[8], lo8[8];
#pragma unroll
        for (int e = 0; e < 8; e++) {
            float w = tile[rl][q * 8 + e];
            __nv_bfloat16 hi = __float2bfloat16(w);
            hi8[e] = hi;
            lo8[e] = __float2bfloat16(w - __bfloat162float(hi));
        }
        size_t o = (size_t)(blk * 32 + rl) * Kc + k0 + q * 8;
        *(uint4*)(g_W_hi + o) = *(uint4*)hi8;
        *(uint4*)(g_W_lo + o) = *(uint4*)lo8;
    }
}

// ---------------------------------------------------------------------------
// prep_x: x[b][t][d] (fp32) -> xs[t][b][d] split bf16.
// ---------------------------------------------------------------------------
__global__ __launch_bounds__(128) void prep_x_kernel(const float* __restrict__ x) {
    int t = blockIdx.x, b = blockIdx.y;
    const float* src = x + ((size_t)b * Tv + t) * Dv;
    size_t dst = ((size_t)t * Bv + b) * Dv;
#pragma unroll
    for (int i = 0; i < 4; i++) {
        int d = threadIdx.x + i * 128;
        float v = src[d];
        __nv_bfloat16 hi = __float2bfloat16(v);
        g_xs_hi[dst + d] = hi;
        g_xs_lo[dst + d] = __float2bfloat16(v - __bfloat162float(hi));
    }
}

// ---------------------------------------------------------------------------
// xproj_mma: P[m][r] = xs[m][:] . W[r][1024:1536]^T + bias (permuted cols),
// 3-term bf16 split. Tile 128m x 64n, K=512 in 4 chunks, 2-stage cp.async.
// ---------------------------------------------------------------------------
#define XKC    128
#define XNCH   4
#define XA_HI  0
#define XA_LO  32768
#define XB_HI  65536
#define XB_LO  81920
#define XST_SZ 98304
#define XPROJ_SMEM (2 * XST_SZ)   // 196608

__global__ __launch_bounds__(256) void xproj_mma(const float* __restrict__ bias)
{
    extern __shared__ __align__(1024) char smem[];
    uint32_t sbase = smem_to_u32(smem);

    const int tid  = threadIdx.x;
    const int wid  = tid >> 5;
    const int lane = tid & 31;
    const int nt   = blockIdx.x;
    const int mt   = blockIdx.y;

    const __nv_bfloat16* A_hi = g_xs_hi + (size_t)mt * 128 * Dv;
    const __nv_bfloat16* A_lo = g_xs_lo + (size_t)mt * 128 * Dv;
    const __nv_bfloat16* B_hi = g_W_hi + (size_t)(nt * 64) * Kc + Uv;
    const __nv_bfloat16* B_lo = g_W_lo + (size_t)(nt * 64) * Kc + Uv;

    const int la_r = tid >> 4;
    const int la_q = tid & 15;

#define ISSUE_X(c)                                                              \
    {                                                                           \
        uint32_t st = sbase + ((c) & 1) * XST_SZ;                               \
        _Pragma("unroll")                                                       \
        for (int i = 0; i < 8; i++) {                                           \
            int r = la_r + i * 16;                                              \
            uint32_t off = swz(r, la_q * 16);                                   \
            cp16(st + XA_HI + off, A_hi + (size_t)r * Dv + (c) * XKC + la_q * 8); \
            cp16(st + XA_LO + off, A_lo + (size_t)r * Dv + (c) * XKC + la_q * 8); \
        }                                                                       \
        _Pragma("unroll")                                                       \
        for (int i = 0; i < 4; i++) {                                           \
            int r = la_r + i * 16;                                              \
            uint32_t off = swz(r, la_q * 16);                                   \
            cp16(st + XB_HI + off, B_hi + (size_t)r * Kc + (c) * XKC + la_q * 8); \
            cp16(st + XB_LO + off, B_lo + (size_t)r * Kc + (c) * XKC + la_q * 8); \
        }                                                                       \
        CP_COMMIT();                                                            \
    }

    const int m0 = (wid >> 1) * 32;
    const int n0 = (wid & 1) * 32;
    const int a_row = m0 + (lane & 15);
    const int a_cb  = (lane >> 4) * 16;
    const int b_row = n0 + ((lane >> 4) << 3) + (lane & 7);
    const int b_cb  = ((lane >> 3) & 1) * 16;

    float d[2][4][4];
#pragma unroll
    for (int i = 0; i < 2; i++)
#pragma unroll
        for (int j = 0; j < 4; j++)
#pragma unroll
            for (int e = 0; e < 4; e++) d[i][j][e] = 0.0f;

    ISSUE_X(0);

    for (int c = 0; c < XNCH; c++) {
        if (c + 1 < XNCH) { ISSUE_X(c + 1); CP_WAIT1(); } else { CP_WAIT0(); }
        __syncthreads();

        uint32_t stb = sbase + (c & 1) * XST_SZ;
#pragma unroll
        for (int ks = 0; ks < XKC / 16; ks++) {
            uint32_t ah[8], al[8], bh[8], bl[8];
            uint32_t ao0 = swz(a_row, ks * 32 + a_cb);
            uint32_t ao1 = swz(a_row + 16, ks * 32 + a_cb);
            uint32_t bo0 = swz(b_row, ks * 32 + b_cb);
            uint32_t bo1 = swz(b_row + 16, ks * 32 + b_cb);
            ldsm_x4(ah[0], ah[1], ah[2], ah[3], stb + XA_HI + ao0);
            ldsm_x4(ah[4], ah[5], ah[6], ah[7], stb + XA_HI + ao1);
            ldsm_x4(al[0], al[1], al[2], al[3], stb + XA_LO + ao0);
            ldsm_x4(al[4], al[5], al[6], al[7], stb + XA_LO + ao1);
            ldsm_x4(bh[0], bh[1], bh[2], bh[3], stb + XB_HI + bo0);
            ldsm_x4(bh[4], bh[5], bh[6], bh[7], stb + XB_HI + bo1);
            ldsm_x4(bl[0], bl[1], bl[2], bl[3], stb + XB_LO + bo0);
            ldsm_x4(bl[4], bl[5], bl[6], bl[7], stb + XB_LO + bo1);

#pragma unroll
            for (int mi = 0; mi < 2; mi++)
#pragma unroll
                for (int ng = 0; ng < 4; ng++)
                    mma_bf16(d[mi][ng], ah[mi*4+0], ah[mi*4+1], ah[mi*4+2], ah[mi*4+3],
                             bh[ng*2], bh[ng*2+1]);
#pragma unroll
            for (int mi = 0; mi < 2; mi++)
#pragma unroll
                for (int ng = 0; ng < 4; ng++)
                    mma_bf16(d[mi][ng], ah[mi*4+0], ah[mi*4+1], ah[mi*4+2], ah[mi*4+3],
                             bl[ng*2], bl[ng*2+1]);
#pragma unroll
            for (int mi = 0; mi < 2; mi++)
#pragma unroll
                for (int ng = 0; ng < 4; ng++)
                    mma_bf16(d[mi][ng], al[mi*4+0], al[mi*4+1], al[mi*4+2], al[mi*4+3],
                             bh[ng*2], bh[ng*2+1]);
        }
        __syncthreads();
    }

    float* ps = (float*)smem;   // 128 x 66
#pragma unroll
    for (int mi = 0; mi < 2; mi++) {
        int row0 = m0 + mi * 16 + (lane >> 2);
        int cbase = (lane & 3) * 2;
#pragma unroll
        for (int ng = 0; ng < 4; ng++) {
            int cc = n0 + ng * 8 + cbase;
            ps[row0 * 66 + cc]           = d[mi][ng][0];
            ps[row0 * 66 + cc + 1]       = d[mi][ng][1];
            ps[(row0 + 8) * 66 + cc]     = d[mi][ng][2];
            ps[(row0 + 8) * 66 + cc + 1] = d[mi][ng][3];
        }
    }
    __syncthreads();

#pragma unroll
    for (int i = 0; i < 8; i++) {
        int idx = tid + i * 256;
        int row = idx >> 4;
        int c4  = (idx & 15) * 4;
        float4 v;
        float* pp = &ps[row * 66 + c4];
        v.x = pp[0]; v.y = pp[1]; v.z = pp[2]; v.w = pp[3];
        float* ve = &v.x;
#pragma unroll
        for (int e = 0; e < 4; e++) {
            int r = nt * 64 + c4 + e;
            int orig = (((r & 31) >> 3) << 10) + ((r >> 5) << 3) + (r & 7);
            ve[e] += bias[orig];
        }
        size_t mrow = (size_t)mt * 128 + row;
        *(float4*)(g_P + mrow * Gv + nt * 64 + c4) = v;
    }
}

// ---------------------------------------------------------------------------
// Persistent LSTM recurrence. 128 CTAs x 256 threads, 1 CTA/SM.
// W slice (32 gate-rows x 1024 K, hi+lo, swizzled) resident in SMEM: 131072 B.
// Per step: stream h (hi+lo) in 8 chunks of 128 K, double-buffered cp.async
// (2 x 32768 B at offset 131072). Warp K-split mainloop, fused pointwise,
// monotonic-counter grid barrier.
// SMEM total: 196608 B.
// ---------------------------------------------------------------------------
#define KC      128
#define NCH     8            // 1024 / 128
#define W_SM    0            // W: part*65536 + chunk*8192 + swz(row32, colb)
#define H_SM    131072       // h: buf*32768 + part*16384 + swz(row64, colb)
#define PERS_SMEM 196608

__global__ __launch_bounds__(256) void lstm_persist(float* __restrict__ out)
{
    extern __shared__ __align__(1024) char smem[];
    uint32_t sbase = smem_to_u32(smem);

    const int tid  = threadIdx.x;
    const int wid  = tid >> 5;
    const int lane = tid & 31;
    const int blk  = blockIdx.x;

    const __nv_bfloat16* Wg_hi = g_W_hi + (size_t)blk * 32 * Kc;
    const __nv_bfloat16* Wg_lo = g_W_lo + (size_t)blk * 32 * Kc;

    // ---- one-time W preload into swizzled SMEM (4096 16B-units per part) ----
    for (int i = tid; i < 4096; i += 256) {
        int r = i >> 7;            // 0..31
        int q = i & 127;           // 16B unit within 1024 K
        int c = q >> 4;            // chunk
        int qq = q & 15;
        uint32_t off = W_SM + c * 8192 + swz(r, qq * 16);
        cp16(sbase + off,         Wg_hi + (size_t)r * Kc + q * 8);
        cp16(sbase + 65536 + off, Wg_lo + (size_t)r * Kc + q * 8);
    }
    CP_COMMIT(); CP_WAIT0();
    __syncthreads();

    const int la_r = tid >> 4;     // 0..15
    const int la_q = tid & 15;

#define ISSUE_H(Hhi, Hlo, c)                                                     \
    {                                                                            \
        uint32_t st = sbase + H_SM + ((c) & 1) * 32768;                          \
        _Pragma("unroll")                                                        \
        for (int i = 0; i < 4; i++) {                                            \
            int r = la_r + i * 16;                                               \
            uint32_t off = swz(r, la_q * 16);                                    \
            cp16(st + off,         (Hhi) + (size_t)r * Uv + (c) * KC + la_q * 8);\
            cp16(st + 16384 + off, (Hlo) + (size_t)r * Uv + (c) * KC + la_q * 8);\
        }                                                                        \
        CP_COMMIT();                                                             \
    }

    const int m0  = (wid & 3) * 16;
    const int ksh = wid >> 2;
    const int a_row = m0 + (lane & 15);
    const int a_cb  = (lane >> 4) * 16;
    const int b_row = ((lane >> 4) << 3) + (lane & 7);   // 0..15
    const int b_cb  = ((lane >> 3) & 1) * 16;

    for (int t = 0; t < Tv; t++) {
        const __nv_bfloat16* H_hi = g_h_hi[t & 1];
        const __nv_bfloat16* H_lo = g_h_lo[t & 1];

        float d[4][4];
#pragma unroll
        for (int i = 0; i < 4; i++)
#pragma unroll
            for (int j = 0; j < 4; j++) d[i][j] = 0.0f;

        ISSUE_H(H_hi, H_lo, 0);

        for (int c = 0; c < NCH; c++) {
            if (c + 1 < NCH) { ISSUE_H(H_hi, H_lo, c + 1); CP_WAIT1(); }
            else             { CP_WAIT0(); }
            __syncthreads();

            uint32_t hb = sbase + H_SM + (c & 1) * 32768;
            uint32_t wb = sbase + W_SM + c * 8192;
#pragma unroll
            for (int ks = 0; ks < 4; ks++) {
                int k16 = ksh * 4 + ks;
                uint32_t ah[4], al[4], bh[8], bl[8];
                uint32_t ao  = swz(a_row, k16 * 32 + a_cb);
                uint32_t bo0 = swz(b_row, k16 * 32 + b_cb);
                uint32_t bo1 = swz(b_row + 16, k16 * 32 + b_cb);
                ldsm_x4(ah[0], ah[1], ah[2], ah[3], hb + ao);
                ldsm_x4(al[0], al[1], al[2], al[3], hb + 16384 + ao);
                ldsm_x4(bh[0], bh[1], bh[2], bh[3], wb + bo0);
                ldsm_x4(bh[4], bh[5], bh[6], bh[7], wb + bo1);
                ldsm_x4(bl[0], bl[1], bl[2], bl[3], wb + 65536 + bo0);
                ldsm_x4(bl[4], bl[5], bl[6], bl[7], wb + 65536 + bo1);

#pragma unroll
                for (int ng = 0; ng < 4; ng++)
                    mma_bf16(d[ng], ah[0], ah[1], ah[2], ah[3], bh[ng*2], bh[ng*2+1]);
#pragma unroll
                for (int ng = 0; ng < 4; ng++)
                    mma_bf16(d[ng], ah[0], ah[1], ah[2], ah[3], bl[ng*2], bl[ng*2+1]);
#pragma unroll
                for (int ng = 0; ng < 4; ng++)
                    mma_bf16(d[ng], al[0], al[1], al[2], al[3], bh[ng*2], bh[ng*2+1]);
            }
            __syncthreads();
        }

        // merge the two ks-halves via SMEM (overlay h buffer 0)
        float* gsA = (float*)(smem + H_SM);     // [64][33]
        float* gsB = gsA + 64 * 33;
        {
            float* g = ksh ? gsB : gsA;
            int row0 = m0 + (lane >> 2);
            int cbase = (lane & 3) * 2;
#pragma unroll
            for (int ng = 0; ng < 4; ng++) {
                int cc = ng * 8 + cbase;
                g[row0 * 33 + cc]           = d[ng][0];
                g[row0 * 33 + cc + 1]       = d[ng][1];
                g[(row0 + 8) * 33 + cc]     = d[ng][2];
                g[(row0 + 8) * 33 + cc + 1] = d[ng][3];
            }
        }
        __syncthreads();

        // fused LSTM pointwise: 64 batches x 8 units = 512 pairs, 2/thread
        __nv_bfloat16* nh_hi = g_h_hi[(t + 1) & 1];
        __nv_bfloat16* nh_lo = g_h_lo[(t + 1) & 1];
#pragma unroll
        for (int i = 0; i < 2; i++) {
            int p = tid + i * 256;
            int b = p >> 3;
            int j = p & 7;
            int u = blk * 8 + j;
            const float* Pb = g_P + ((size_t)t * Bv + b) * Gv + blk * 32;

            float xi = gsA[b * 33 + 0 * 8 + j] + gsB[b * 33 + 0 * 8 + j] + Pb[0 * 8 + j];
            float xf = gsA[b * 33 + 1 * 8 + j] + gsB[b * 33 + 1 * 8 + j] + Pb[1 * 8 + j];
            float xg = gsA[b * 33 + 2 * 8 + j] + gsB[b * 33 + 2 * 8 + j] + Pb[2 * 8 + j];
            float xo = gsA[b * 33 + 3 * 8 + j] + gsB[b * 33 + 3 * 8 + j] + Pb[3 * 8 + j];

            float ig = 1.0f / (1.0f + expf(-xi));
            float fg = 1.0f / (1.0f + expf(-xf));
            float gg = tanhf(xg);
            float og = 1.0f / (1.0f + expf(-xo));

            int idx = b * Uv + u;
            float cc = fg * g_c[idx] + ig * gg;
            g_c[idx] = cc;
            float h = og * tanhf(cc);

            out[((size_t)b * Tv + t) * Uv + u] = h;
            __nv_bfloat16 hh = __float2bfloat16(h);
            nh_hi[idx] = hh;
            nh_lo[idx] = __float2bfloat16(h - __bfloat162float(hh));
        }

        // grid barrier (skip after final step)
        __syncthreads();
        if (t + 1 < Tv) {
            if (tid == 0) {
                __threadfence();
                atomicAdd(&g_count, 1);
                int target = (t + 1) * NBLK;
                int v;
                do {
                    asm volatile("ld.acquire.gpu.global.b32 %0, [%1];"
                                 : "=r"(v) : "l"(&g_count));
                } while (v < target);
            }
            __syncthreads();
        }
    }
}

// ---------------------------------------------------------------------------
// Launch: init -> prep_w -> prep_x -> xproj_mma -> ONE persistent kernel
// ---------------------------------------------------------------------------
extern "C" void kernel_launch(void* const* d_in, const int* in_sizes, int n_in,
                              void* d_out, int out_size)
{
    const float* x    = (const float*)d_in[0];   // [64, 512, 512]
    const float* Wx   = (const float*)d_in[1];   // [512, 4096]
    const float* Wh   = (const float*)d_in[2];   // [1024, 4096]
    const float* bias = (const float*)d_in[3];   // [4096]
    float* out = (float*)d_out;                  // [64, 512, 1024]

    static int configured = 0;
    if (!configured) {
        cudaFuncSetAttribute(lstm_persist,
                             cudaFuncAttributeMaxDynamicSharedMemorySize, PERS_SMEM);
        cudaFuncSetAttribute(xproj_mma,
                             cudaFuncAttributeMaxDynamicSharedMemorySize, XPROJ_SMEM);
        configured = 1;
    }

    init_kernel<<<(Bv * Uv + 255) / 256, 256>>>();

    dim3 wgrid(Kc / 128, Gv / 32);
    prep_w_kernel<<<wgrid, 256>>>(Wh, Wx);

    dim3 xgrid(Tv, Bv);
    prep_x_kernel<<<xgrid, 128>>>(x);

    dim3 pgrid(Gv / 64, (Tv * Bv) / 128);
    xproj_mma<<<pgrid, 256, XPROJ_SMEM>>>(bias);

    lstm_persist<<<NBLK, 256, PERS_SMEM>>>(out);
}